// round 7
// baseline (speedup 1.0000x reference)
#include <cuda_runtime.h>
#include <math.h>

#define B   128
#define H   2048
#define E   64
#define I   768
#define TWO_I 1536
#define TOPK 8

#define KB  32      // K chunk
#define NT  128     // N tile (rows of weight matrix per block)
#define MT  32      // M tile (tokens per block)

// -------- scratch (no allocations allowed; __device__ globals are the sanctioned path) -----
__device__ float g_routing[B * E];      // dense routing weights (only topk entries ever read)
__device__ int   g_count[E];            // tokens routed to each expert
__device__ int   g_tokens[E * B];       // token list per expert
__device__ float g_inter[(size_t)E * B * I];  // silu(gate)*up per (expert, slot)  ~25 MB

// ============================================================================
// Kernel 0: zero output + expert counters
// ============================================================================
__global__ void k_zero(float* __restrict__ out) {
    int idx = blockIdx.x * blockDim.x + threadIdx.x;
    if (idx < B * H) out[idx] = 0.f;
    if (idx < E) g_count[idx] = 0;
}

// ============================================================================
// Kernel 1: routing. One block per token. 256 threads = 8 warps, each warp
// computes 8 expert logits via coalesced float4 dot + shfl reduce.
// Top-8 + weight normalization done serially by thread 0 (64 elems, trivial).
// ============================================================================
__global__ void k_route(const float* __restrict__ x, const float* __restrict__ gw) {
    int b    = blockIdx.x;
    int tid  = threadIdx.x;
    int warp = tid >> 5;
    int lane = tid & 31;

    __shared__ float sl[E];

    const float4* xr = (const float4*)(x + (size_t)b * H);
    for (int j = 0; j < 8; ++j) {
        int e = warp * 8 + j;
        const float4* gr = (const float4*)(gw + (size_t)e * H);
        float acc = 0.f;
        for (int t = lane; t < H / 4; t += 32) {
            float4 xv = xr[t];
            float4 gv = gr[t];
            acc += xv.x * gv.x + xv.y * gv.y + xv.z * gv.z + xv.w * gv.w;
        }
        #pragma unroll
        for (int o = 16; o > 0; o >>= 1) acc += __shfl_xor_sync(0xffffffffu, acc, o);
        if (lane == 0) sl[e] = acc;
    }
    __syncthreads();

    if (tid == 0) {
        float m = sl[0];
        #pragma unroll
        for (int e = 1; e < E; ++e) m = fmaxf(m, sl[e]);
        float p[E];
        #pragma unroll
        for (int e = 0; e < E; ++e) p[e] = expf(sl[e] - m);

        int   sel[TOPK];
        float val[TOPK];
        float ssum = 0.f;
        for (int k = 0; k < TOPK; ++k) {
            int   best = 0;
            float bv   = -1.f;
            for (int e = 0; e < E; ++e) {
                if (p[e] > bv) { bv = p[e]; best = e; }
            }
            sel[k] = best;
            val[k] = bv;
            ssum  += bv;
            p[best] = -2.f;
        }
        for (int k = 0; k < TOPK; ++k) {
            int e = sel[k];
            g_routing[b * E + e] = val[k] / ssum;
            int pos = atomicAdd(&g_count[e], 1);
            g_tokens[e * B + pos] = b;
        }
    }
}

// ============================================================================
// Kernel 2: per-expert up-projection, gate+up fused, silu applied, write inter.
// Grid: (I/NT=6, E=64, B/MT=4). Block: 128 threads.
// Tile: 128 intermediate rows (gate AND up) x 32 tokens x K chunks of 32.
// Per thread: 8 n x 4 m x 2 (gate/up) = 64 fp32 accumulators.
// ============================================================================
__global__ void __launch_bounds__(128, 2)
k_up(const float* __restrict__ x, const float* __restrict__ w1) {
    int e   = blockIdx.y;
    int cnt = g_count[e];
    int m0  = blockIdx.z * MT;
    if (m0 >= cnt) return;
    int M   = min(MT, cnt - m0);
    int n0  = blockIdx.x * NT;           // i offset in [0, I)
    int tid = threadIdx.x;

    __shared__ float wg[KB][NT + 4];     // [kk][n], stride 132 (16B aligned rows)
    __shared__ float wu[KB][NT + 4];
    __shared__ float xs[KB][MT + 4];     // [kk][m], stride 36
    __shared__ int   toks[MT];

    if (tid < MT) toks[tid] = (tid < M) ? g_tokens[e * B + m0 + tid] : -1;

    const float* w1g = w1 + ((size_t)e * TWO_I + n0) * H;
    const float* w1u = w1 + ((size_t)e * TWO_I + I + n0) * H;

    int ng = tid & 15;    // 16 n-groups
    int mg = tid >> 4;    // 8 m-groups
    int nb = ng * 8;
    int mb = mg * 4;

    float ag[4][8], au[4][8];
    #pragma unroll
    for (int i = 0; i < 4; ++i)
        #pragma unroll
        for (int j = 0; j < 8; ++j) { ag[i][j] = 0.f; au[i][j] = 0.f; }

    for (int k0 = 0; k0 < H; k0 += KB) {
        __syncthreads();
        // weight tiles: 128 rows x 32 floats = 1024 float4 per tile, 8 per thread
        #pragma unroll
        for (int r = 0; r < 8; ++r) {
            int idx = tid + r * 128;
            int n   = idx >> 3;
            int kq  = idx & 7;
            int kk  = kq * 4;
            float4 v = *(const float4*)(w1g + (size_t)n * H + k0 + kq * 4);
            wg[kk + 0][n] = v.x; wg[kk + 1][n] = v.y; wg[kk + 2][n] = v.z; wg[kk + 3][n] = v.w;
            v = *(const float4*)(w1u + (size_t)n * H + k0 + kq * 4);
            wu[kk + 0][n] = v.x; wu[kk + 1][n] = v.y; wu[kk + 2][n] = v.z; wu[kk + 3][n] = v.w;
        }
        // token tile: 32 m x 32 floats = 256 float4, 2 per thread
        #pragma unroll
        for (int r = 0; r < 2; ++r) {
            int idx = tid + r * 128;
            int m   = idx >> 3;
            int kq  = idx & 7;
            int kk  = kq * 4;
            int t   = toks[m];
            float4 v = make_float4(0.f, 0.f, 0.f, 0.f);
            if (t >= 0) v = *(const float4*)(x + (size_t)t * H + k0 + kq * 4);
            xs[kk + 0][m] = v.x; xs[kk + 1][m] = v.y; xs[kk + 2][m] = v.z; xs[kk + 3][m] = v.w;
        }
        __syncthreads();

        #pragma unroll 8
        for (int kk = 0; kk < KB; ++kk) {
            float4 xv = *(const float4*)&xs[kk][mb];
            float4 g0 = *(const float4*)&wg[kk][nb];
            float4 g1 = *(const float4*)&wg[kk][nb + 4];
            float4 u0 = *(const float4*)&wu[kk][nb];
            float4 u1 = *(const float4*)&wu[kk][nb + 4];
            float xm[4] = {xv.x, xv.y, xv.z, xv.w};
            float gv[8] = {g0.x, g0.y, g0.z, g0.w, g1.x, g1.y, g1.z, g1.w};
            float uv[8] = {u0.x, u0.y, u0.z, u0.w, u1.x, u1.y, u1.z, u1.w};
            #pragma unroll
            for (int i = 0; i < 4; ++i)
                #pragma unroll
                for (int j = 0; j < 8; ++j) {
                    ag[i][j] += xm[i] * gv[j];
                    au[i][j] += xm[i] * uv[j];
                }
        }
    }

    #pragma unroll
    for (int i = 0; i < 4; ++i) {
        int m = mb + i;
        if (m >= M) continue;
        float* dst = g_inter + ((size_t)e * B + m0 + m) * I + n0 + nb;
        #pragma unroll
        for (int j = 0; j < 8; ++j) {
            float hg = ag[i][j];
            float hu = au[i][j];
            float s  = hg / (1.f + expf(-hg));   // silu
            dst[j]   = s * hu;
        }
    }
}

// ============================================================================
// Kernel 3: per-expert down-projection, scaled by routing weight, atomicAdd
// into out. Grid: (H/NT=16, E=64, B/MT=4). Block: 128 threads. K = I = 768.
// ============================================================================
__global__ void __launch_bounds__(128, 2)
k_down(const float* __restrict__ w2, float* __restrict__ out) {
    int e   = blockIdx.y;
    int cnt = g_count[e];
    int m0  = blockIdx.z * MT;
    if (m0 >= cnt) return;
    int M   = min(MT, cnt - m0);
    int n0  = blockIdx.x * NT;           // h offset in [0, H)
    int tid = threadIdx.x;

    __shared__ float ws[KB][NT + 4];
    __shared__ float xs[KB][MT + 4];
    __shared__ int   toks[MT];
    __shared__ float rw[MT];

    if (tid < MT) {
        int t = (tid < M) ? g_tokens[e * B + m0 + tid] : -1;
        toks[tid] = t;
        rw[tid]   = (t >= 0) ? g_routing[t * E + e] : 0.f;
    }

    const float* wp = w2 + (size_t)e * H * I + (size_t)n0 * I;
    const float* ip = g_inter + ((size_t)e * B + m0) * I;

    int ng = tid & 15;
    int mg = tid >> 4;
    int nb = ng * 8;
    int mb = mg * 4;

    float acc[4][8];
    #pragma unroll
    for (int i = 0; i < 4; ++i)
        #pragma unroll
        for (int j = 0; j < 8; ++j) acc[i][j] = 0.f;

    for (int k0 = 0; k0 < I; k0 += KB) {   // 24 chunks
        __syncthreads();
        #pragma unroll
        for (int r = 0; r < 8; ++r) {
            int idx = tid + r * 128;
            int n   = idx >> 3;
            int kq  = idx & 7;
            int kk  = kq * 4;
            float4 v = *(const float4*)(wp + (size_t)n * I + k0 + kq * 4);
            ws[kk + 0][n] = v.x; ws[kk + 1][n] = v.y; ws[kk + 2][n] = v.z; ws[kk + 3][n] = v.w;
        }
        #pragma unroll
        for (int r = 0; r < 2; ++r) {
            int idx = tid + r * 128;
            int m   = idx >> 3;
            int kq  = idx & 7;
            int kk  = kq * 4;
            float4 v = make_float4(0.f, 0.f, 0.f, 0.f);
            if (m < M) v = *(const float4*)(ip + (size_t)m * I + k0 + kq * 4);
            xs[kk + 0][m] = v.x; xs[kk + 1][m] = v.y; xs[kk + 2][m] = v.z; xs[kk + 3][m] = v.w;
        }
        __syncthreads();

        #pragma unroll 8
        for (int kk = 0; kk < KB; ++kk) {
            float4 xv = *(const float4*)&xs[kk][mb];
            float4 w0 = *(const float4*)&ws[kk][nb];
            float4 w1v = *(const float4*)&ws[kk][nb + 4];
            float xm[4] = {xv.x, xv.y, xv.z, xv.w};
            float wv[8] = {w0.x, w0.y, w0.z, w0.w, w1v.x, w1v.y, w1v.z, w1v.w};
            #pragma unroll
            for (int i = 0; i < 4; ++i)
                #pragma unroll
                for (int j = 0; j < 8; ++j)
                    acc[i][j] += xm[i] * wv[j];
        }
    }

    #pragma unroll
    for (int i = 0; i < 4; ++i) {
        int m = mb + i;
        if (m >= M) continue;
        float s = rw[m];
        int   b = toks[m];
        float* dst = out + (size_t)b * H + n0 + nb;
        #pragma unroll
        for (int j = 0; j < 8; ++j)
            atomicAdd(&dst[j], s * acc[i][j]);
    }
}

// ============================================================================
// Launch
// ============================================================================
extern "C" void kernel_launch(void* const* d_in, const int* in_sizes, int n_in,
                              void* d_out, int out_size) {
    const float* x  = (const float*)d_in[0];   // (128, 2048)
    const float* gw = (const float*)d_in[1];   // (64, 2048)
    const float* w1 = (const float*)d_in[2];   // (64, 1536, 2048)
    const float* w2 = (const float*)d_in[3];   // (64, 2048, 768)
    float* out = (float*)d_out;                // (128, 1, 2048)

    k_zero<<<(B * H + 255) / 256, 256>>>(out);
    k_route<<<B, 256>>>(x, gw);

    dim3 gA(I / NT, E, B / MT);    // (6, 64, 4)
    k_up<<<gA, 128>>>(x, w1);

    dim3 gB(H / NT, E, B / MT);    // (16, 64, 4)
    k_down<<<gB, 128>>>(w2, out);
}

// round 8
// speedup vs baseline: 1.0043x; 1.0043x over previous
#include <cuda_runtime.h>
#include <math.h>

#define B   128
#define H   2048
#define E   64
#define I   768
#define TWO_I 1536
#define TOPK 8

#define KB  32      // K chunk
#define NT  128     // N tile (rows of weight matrix per block)
#define MT  32      // M tile (tokens per block)

// -------- scratch (no allocations allowed; __device__ globals are the sanctioned path) -----
__device__ float g_routing[B * E];      // dense routing weights (only topk entries ever read)
__device__ int   g_count[E];            // tokens routed to each expert
__device__ int   g_tokens[E * B];       // token list per expert
__device__ float g_inter[(size_t)E * B * I];  // silu(gate)*up per (expert, slot)  ~25 MB

// ============================================================================
// Kernel 0: zero output + expert counters
// ============================================================================
__global__ void k_zero(float* __restrict__ out) {
    int idx = blockIdx.x * blockDim.x + threadIdx.x;
    if (idx < B * H) out[idx] = 0.f;
    if (idx < E) g_count[idx] = 0;
}

// ============================================================================
// Kernel 1: routing. One block per token. 256 threads = 8 warps, each warp
// computes 8 expert logits via coalesced float4 dot + shfl reduce.
// Top-8 + weight normalization done serially by thread 0 (64 elems, trivial).
// ============================================================================
__global__ void k_route(const float* __restrict__ x, const float* __restrict__ gw) {
    int b    = blockIdx.x;
    int tid  = threadIdx.x;
    int warp = tid >> 5;
    int lane = tid & 31;

    __shared__ float sl[E];

    const float4* xr = (const float4*)(x + (size_t)b * H);
    for (int j = 0; j < 8; ++j) {
        int e = warp * 8 + j;
        const float4* gr = (const float4*)(gw + (size_t)e * H);
        float acc = 0.f;
        for (int t = lane; t < H / 4; t += 32) {
            float4 xv = xr[t];
            float4 gv = gr[t];
            acc += xv.x * gv.x + xv.y * gv.y + xv.z * gv.z + xv.w * gv.w;
        }
        #pragma unroll
        for (int o = 16; o > 0; o >>= 1) acc += __shfl_xor_sync(0xffffffffu, acc, o);
        if (lane == 0) sl[e] = acc;
    }
    __syncthreads();

    if (tid == 0) {
        float m = sl[0];
        #pragma unroll
        for (int e = 1; e < E; ++e) m = fmaxf(m, sl[e]);
        float p[E];
        #pragma unroll
        for (int e = 0; e < E; ++e) p[e] = expf(sl[e] - m);

        int   sel[TOPK];
        float val[TOPK];
        float ssum = 0.f;
        for (int k = 0; k < TOPK; ++k) {
            int   best = 0;
            float bv   = -1.f;
            for (int e = 0; e < E; ++e) {
                if (p[e] > bv) { bv = p[e]; best = e; }
            }
            sel[k] = best;
            val[k] = bv;
            ssum  += bv;
            p[best] = -2.f;
        }
        for (int k = 0; k < TOPK; ++k) {
            int e = sel[k];
            g_routing[b * E + e] = val[k] / ssum;
            int pos = atomicAdd(&g_count[e], 1);
            g_tokens[e * B + pos] = b;
        }
    }
}

// ============================================================================
// Kernel 2: per-expert up-projection, gate+up fused, silu applied, write inter.
// Grid: (I/NT=6, E=64, B/MT=4). Block: 128 threads.
// Tile: 128 intermediate rows (gate AND up) x 32 tokens x K chunks of 32.
// Per thread: 8 n x 4 m x 2 (gate/up) = 64 fp32 accumulators.
// ============================================================================
__global__ void __launch_bounds__(128, 2)
k_up(const float* __restrict__ x, const float* __restrict__ w1) {
    int e   = blockIdx.y;
    int cnt = g_count[e];
    int m0  = blockIdx.z * MT;
    if (m0 >= cnt) return;
    int M   = min(MT, cnt - m0);
    int n0  = blockIdx.x * NT;           // i offset in [0, I)
    int tid = threadIdx.x;

    __shared__ float wg[KB][NT + 4];     // [kk][n], stride 132 (16B aligned rows)
    __shared__ float wu[KB][NT + 4];
    __shared__ float xs[KB][MT + 4];     // [kk][m], stride 36
    __shared__ int   toks[MT];

    if (tid < MT) toks[tid] = (tid < M) ? g_tokens[e * B + m0 + tid] : -1;

    const float* w1g = w1 + ((size_t)e * TWO_I + n0) * H;
    const float* w1u = w1 + ((size_t)e * TWO_I + I + n0) * H;

    int ng = tid & 15;    // 16 n-groups
    int mg = tid >> 4;    // 8 m-groups
    int nb = ng * 8;
    int mb = mg * 4;

    float ag[4][8], au[4][8];
    #pragma unroll
    for (int i = 0; i < 4; ++i)
        #pragma unroll
        for (int j = 0; j < 8; ++j) { ag[i][j] = 0.f; au[i][j] = 0.f; }

    for (int k0 = 0; k0 < H; k0 += KB) {
        __syncthreads();
        // weight tiles: 128 rows x 32 floats = 1024 float4 per tile, 8 per thread
        #pragma unroll
        for (int r = 0; r < 8; ++r) {
            int idx = tid + r * 128;
            int n   = idx >> 3;
            int kq  = idx & 7;
            int kk  = kq * 4;
            float4 v = *(const float4*)(w1g + (size_t)n * H + k0 + kq * 4);
            wg[kk + 0][n] = v.x; wg[kk + 1][n] = v.y; wg[kk + 2][n] = v.z; wg[kk + 3][n] = v.w;
            v = *(const float4*)(w1u + (size_t)n * H + k0 + kq * 4);
            wu[kk + 0][n] = v.x; wu[kk + 1][n] = v.y; wu[kk + 2][n] = v.z; wu[kk + 3][n] = v.w;
        }
        // token tile: 32 m x 32 floats = 256 float4, 2 per thread
        #pragma unroll
        for (int r = 0; r < 2; ++r) {
            int idx = tid + r * 128;
            int m   = idx >> 3;
            int kq  = idx & 7;
            int kk  = kq * 4;
            int t   = toks[m];
            float4 v = make_float4(0.f, 0.f, 0.f, 0.f);
            if (t >= 0) v = *(const float4*)(x + (size_t)t * H + k0 + kq * 4);
            xs[kk + 0][m] = v.x; xs[kk + 1][m] = v.y; xs[kk + 2][m] = v.z; xs[kk + 3][m] = v.w;
        }
        __syncthreads();

        #pragma unroll 8
        for (int kk = 0; kk < KB; ++kk) {
            float4 xv = *(const float4*)&xs[kk][mb];
            float4 g0 = *(const float4*)&wg[kk][nb];
            float4 g1 = *(const float4*)&wg[kk][nb + 4];
            float4 u0 = *(const float4*)&wu[kk][nb];
            float4 u1 = *(const float4*)&wu[kk][nb + 4];
            float xm[4] = {xv.x, xv.y, xv.z, xv.w};
            float gv[8] = {g0.x, g0.y, g0.z, g0.w, g1.x, g1.y, g1.z, g1.w};
            float uv[8] = {u0.x, u0.y, u0.z, u0.w, u1.x, u1.y, u1.z, u1.w};
            #pragma unroll
            for (int i = 0; i < 4; ++i)
                #pragma unroll
                for (int j = 0; j < 8; ++j) {
                    ag[i][j] += xm[i] * gv[j];
                    au[i][j] += xm[i] * uv[j];
                }
        }
    }

    #pragma unroll
    for (int i = 0; i < 4; ++i) {
        int m = mb + i;
        if (m >= M) continue;
        float* dst = g_inter + ((size_t)e * B + m0 + m) * I + n0 + nb;
        #pragma unroll
        for (int j = 0; j < 8; ++j) {
            float hg = ag[i][j];
            float hu = au[i][j];
            float s  = hg / (1.f + expf(-hg));   // silu
            dst[j]   = s * hu;
        }
    }
}

// ============================================================================
// Kernel 3: per-expert down-projection, scaled by routing weight, atomicAdd
// into out. Grid: (H/NT=16, E=64, B/MT=4). Block: 128 threads. K = I = 768.
// ============================================================================
__global__ void __launch_bounds__(128, 2)
k_down(const float* __restrict__ w2, float* __restrict__ out) {
    int e   = blockIdx.y;
    int cnt = g_count[e];
    int m0  = blockIdx.z * MT;
    if (m0 >= cnt) return;
    int M   = min(MT, cnt - m0);
    int n0  = blockIdx.x * NT;           // h offset in [0, H)
    int tid = threadIdx.x;

    __shared__ float ws[KB][NT + 4];
    __shared__ float xs[KB][MT + 4];
    __shared__ int   toks[MT];
    __shared__ float rw[MT];

    if (tid < MT) {
        int t = (tid < M) ? g_tokens[e * B + m0 + tid] : -1;
        toks[tid] = t;
        rw[tid]   = (t >= 0) ? g_routing[t * E + e] : 0.f;
    }

    const float* wp = w2 + (size_t)e * H * I + (size_t)n0 * I;
    const float* ip = g_inter + ((size_t)e * B + m0) * I;

    int ng = tid & 15;
    int mg = tid >> 4;
    int nb = ng * 8;
    int mb = mg * 4;

    float acc[4][8];
    #pragma unroll
    for (int i = 0; i < 4; ++i)
        #pragma unroll
        for (int j = 0; j < 8; ++j) acc[i][j] = 0.f;

    for (int k0 = 0; k0 < I; k0 += KB) {   // 24 chunks
        __syncthreads();
        #pragma unroll
        for (int r = 0; r < 8; ++r) {
            int idx = tid + r * 128;
            int n   = idx >> 3;
            int kq  = idx & 7;
            int kk  = kq * 4;
            float4 v = *(const float4*)(wp + (size_t)n * I + k0 + kq * 4);
            ws[kk + 0][n] = v.x; ws[kk + 1][n] = v.y; ws[kk + 2][n] = v.z; ws[kk + 3][n] = v.w;
        }
        #pragma unroll
        for (int r = 0; r < 2; ++r) {
            int idx = tid + r * 128;
            int m   = idx >> 3;
            int kq  = idx & 7;
            int kk  = kq * 4;
            float4 v = make_float4(0.f, 0.f, 0.f, 0.f);
            if (m < M) v = *(const float4*)(ip + (size_t)m * I + k0 + kq * 4);
            xs[kk + 0][m] = v.x; xs[kk + 1][m] = v.y; xs[kk + 2][m] = v.z; xs[kk + 3][m] = v.w;
        }
        __syncthreads();

        #pragma unroll 8
        for (int kk = 0; kk < KB; ++kk) {
            float4 xv = *(const float4*)&xs[kk][mb];
            float4 w0 = *(const float4*)&ws[kk][nb];
            float4 w1v = *(const float4*)&ws[kk][nb + 4];
            float xm[4] = {xv.x, xv.y, xv.z, xv.w};
            float wv[8] = {w0.x, w0.y, w0.z, w0.w, w1v.x, w1v.y, w1v.z, w1v.w};
            #pragma unroll
            for (int i = 0; i < 4; ++i)
                #pragma unroll
                for (int j = 0; j < 8; ++j)
                    acc[i][j] += xm[i] * wv[j];
        }
    }

    #pragma unroll
    for (int i = 0; i < 4; ++i) {
        int m = mb + i;
        if (m >= M) continue;
        float s = rw[m];
        int   b = toks[m];
        float* dst = out + (size_t)b * H + n0 + nb;
        #pragma unroll
        for (int j = 0; j < 8; ++j)
            atomicAdd(&dst[j], s * acc[i][j]);
    }
}

// ============================================================================
// Launch
// ============================================================================
extern "C" void kernel_launch(void* const* d_in, const int* in_sizes, int n_in,
                              void* d_out, int out_size) {
    const float* x  = (const float*)d_in[0];   // (128, 2048)
    const float* gw = (const float*)d_in[1];   // (64, 2048)
    const float* w1 = (const float*)d_in[2];   // (64, 1536, 2048)
    const float* w2 = (const float*)d_in[3];   // (64, 2048, 768)
    float* out = (float*)d_out;                // (128, 1, 2048)

    k_zero<<<(B * H + 255) / 256, 256>>>(out);
    k_route<<<B, 256>>>(x, gw);

    dim3 gA(I / NT, E, B / MT);    // (6, 64, 4)
    k_up<<<gA, 128>>>(x, w1);

    dim3 gB(H / NT, E, B / MT);    // (16, 64, 4)
    k_down<<<gB, 128>>>(w2, out);
}

// round 9
// speedup vs baseline: 2.1191x; 2.1099x over previous
#include <cuda_runtime.h>
#include <math.h>

#define B     128
#define H     2048
#define E     64
#define I     768
#define TWO_I 1536
#define TOPK  8

#define KB  16      // K chunk (floats)
#define NT  128     // N tile (weight rows per block)
#define MT  32      // M tile (tokens per block)
#define WSTR (NT + 4)   // 132: weight smem row stride (mult of 4, 2-way STS at worst)
#define XSTR (MT + 4)   // 36:  x smem row stride

// -------- scratch (no allocations allowed; __device__ globals) --------------
__device__ float g_routing[B * E];
__device__ int   g_count[E];
__device__ int   g_tokens[E * B];
__device__ float g_inter[(size_t)E * B * I];   // ~25 MB

// ============================================================================
// Kernel 0: zero output + expert counters
// ============================================================================
__global__ void k_zero(float* __restrict__ out) {
    int idx = blockIdx.x * blockDim.x + threadIdx.x;
    if (idx < B * H) out[idx] = 0.f;
    if (idx < E) g_count[idx] = 0;
}

// ============================================================================
// Kernel 1: routing (unchanged — small cost, correct)
// ============================================================================
__global__ void k_route(const float* __restrict__ x, const float* __restrict__ gw) {
    int b    = blockIdx.x;
    int tid  = threadIdx.x;
    int warp = tid >> 5;
    int lane = tid & 31;

    __shared__ float sl[E];

    const float4* xr = (const float4*)(x + (size_t)b * H);
    for (int j = 0; j < 8; ++j) {
        int e = warp * 8 + j;
        const float4* gr = (const float4*)(gw + (size_t)e * H);
        float acc = 0.f;
        for (int t = lane; t < H / 4; t += 32) {
            float4 xv = xr[t];
            float4 gv = gr[t];
            acc += xv.x * gv.x + xv.y * gv.y + xv.z * gv.z + xv.w * gv.w;
        }
        #pragma unroll
        for (int o = 16; o > 0; o >>= 1) acc += __shfl_xor_sync(0xffffffffu, acc, o);
        if (lane == 0) sl[e] = acc;
    }
    __syncthreads();

    if (tid == 0) {
        float m = sl[0];
        #pragma unroll
        for (int e = 1; e < E; ++e) m = fmaxf(m, sl[e]);
        float p[E];
        #pragma unroll
        for (int e = 0; e < E; ++e) p[e] = expf(sl[e] - m);

        int   sel[TOPK];
        float val[TOPK];
        float ssum = 0.f;
        for (int k = 0; k < TOPK; ++k) {
            int   best = 0;
            float bv   = -1.f;
            for (int e = 0; e < E; ++e)
                if (p[e] > bv) { bv = p[e]; best = e; }
            sel[k] = best; val[k] = bv; ssum += bv; p[best] = -2.f;
        }
        for (int k = 0; k < TOPK; ++k) {
            int e = sel[k];
            g_routing[b * E + e] = val[k] / ssum;
            int pos = atomicAdd(&g_count[e], 1);
            g_tokens[e * B + pos] = b;
        }
    }
}

// ============================================================================
// Kernel 2: up-projection (gate+up fused + silu). Grid (I/NT=6, E, B/MT=4).
// 128 threads. Per-thread frag: 4 m x (4+4) n x 2 matrices = 64 acc.
// Conflict-free fragment map: thread's n = {4ng..4ng+3} u {64+4ng..64+4ng+3}.
// Register-prefetch pipeline over KB=16 chunks.
// ============================================================================
__global__ void __launch_bounds__(128, 3)
k_up(const float* __restrict__ x, const float* __restrict__ w1) {
    int e   = blockIdx.y;
    int cnt = g_count[e];
    int m0  = blockIdx.z * MT;
    if (m0 >= cnt) return;
    int M   = min(MT, cnt - m0);
    int n0  = blockIdx.x * NT;
    int tid = threadIdx.x;
    int warp = tid >> 5;

    __shared__ __align__(16) float wg[KB][WSTR];
    __shared__ __align__(16) float wu[KB][WSTR];
    __shared__ __align__(16) float xs[KB][XSTR];
    __shared__ int toks[MT];

    if (tid < MT) toks[tid] = (tid < M) ? g_tokens[e * B + m0 + tid] : -1;
    __syncthreads();

    int ng = tid & 15;
    int mb = (tid >> 4) * 4;
    bool wactive = (warp * 8) < M;        // warp-uniform padding skip

    // staging map: thread -> (row wn+32r, float4 kq) ; transposed STS
    int wn = tid >> 2;                    // 0..31
    int kq = tid & 3;                     // 0..3
    const float* pg = w1 + ((size_t)e * TWO_I + n0 + wn) * H + 4 * kq;
    const float* pu = pg + (size_t)I * H;
    int  xt     = toks[wn];
    bool xvalid = (xt >= 0);
    const float* px = x + (size_t)(xvalid ? xt : 0) * H + 4 * kq;

    float4 rg[4], ru[4], rx;
    #pragma unroll
    for (int r = 0; r < 4; ++r) {
        rg[r] = *(const float4*)(pg + (size_t)(32 * r) * H);
        ru[r] = *(const float4*)(pu + (size_t)(32 * r) * H);
    }
    rx = xvalid ? *(const float4*)px : make_float4(0.f, 0.f, 0.f, 0.f);

    float ag[4][8], au[4][8];
    #pragma unroll
    for (int i = 0; i < 4; ++i)
        #pragma unroll
        for (int j = 0; j < 8; ++j) { ag[i][j] = 0.f; au[i][j] = 0.f; }

    const int NC = H / KB;                // 128 chunks
    for (int c = 0; c < NC; ++c) {
        __syncthreads();                  // previous FMA done -> safe to overwrite
        #pragma unroll
        for (int r = 0; r < 4; ++r) {
            int n = wn + 32 * r;
            wg[4*kq+0][n] = rg[r].x; wg[4*kq+1][n] = rg[r].y;
            wg[4*kq+2][n] = rg[r].z; wg[4*kq+3][n] = rg[r].w;
            wu[4*kq+0][n] = ru[r].x; wu[4*kq+1][n] = ru[r].y;
            wu[4*kq+2][n] = ru[r].z; wu[4*kq+3][n] = ru[r].w;
        }
        xs[4*kq+0][wn] = rx.x; xs[4*kq+1][wn] = rx.y;
        xs[4*kq+2][wn] = rx.z; xs[4*kq+3][wn] = rx.w;
        __syncthreads();                  // tile ready

        if (c + 1 < NC) {                 // prefetch next chunk (overlaps FMA)
            int k0 = (c + 1) * KB;
            #pragma unroll
            for (int r = 0; r < 4; ++r) {
                rg[r] = *(const float4*)(pg + (size_t)(32 * r) * H + k0);
                ru[r] = *(const float4*)(pu + (size_t)(32 * r) * H + k0);
            }
            rx = xvalid ? *(const float4*)(px + k0) : make_float4(0.f,0.f,0.f,0.f);
        }

        if (wactive) {
            #pragma unroll 4
            for (int kk = 0; kk < KB; ++kk) {
                float4 xv = *(const float4*)&xs[kk][mb];
                float4 g0 = *(const float4*)&wg[kk][4*ng];
                float4 g1 = *(const float4*)&wg[kk][64 + 4*ng];
                float4 u0 = *(const float4*)&wu[kk][4*ng];
                float4 u1 = *(const float4*)&wu[kk][64 + 4*ng];
                float xm4[4] = {xv.x, xv.y, xv.z, xv.w};
                float gv[8]  = {g0.x,g0.y,g0.z,g0.w, g1.x,g1.y,g1.z,g1.w};
                float uv[8]  = {u0.x,u0.y,u0.z,u0.w, u1.x,u1.y,u1.z,u1.w};
                #pragma unroll
                for (int i = 0; i < 4; ++i)
                    #pragma unroll
                    for (int j = 0; j < 8; ++j) {
                        ag[i][j] += xm4[i] * gv[j];
                        au[i][j] += xm4[i] * uv[j];
                    }
            }
        }
    }

    #pragma unroll
    for (int i = 0; i < 4; ++i) {
        int m = mb + i;
        if (m >= M) continue;
        float* dst = g_inter + ((size_t)e * B + m0 + m) * I + n0;
        float4 o0, o1;
        {
            float hg = ag[i][0], hu = au[i][0]; o0.x = (hg / (1.f + expf(-hg))) * hu;
            hg = ag[i][1]; hu = au[i][1];       o0.y = (hg / (1.f + expf(-hg))) * hu;
            hg = ag[i][2]; hu = au[i][2];       o0.z = (hg / (1.f + expf(-hg))) * hu;
            hg = ag[i][3]; hu = au[i][3];       o0.w = (hg / (1.f + expf(-hg))) * hu;
            hg = ag[i][4]; hu = au[i][4];       o1.x = (hg / (1.f + expf(-hg))) * hu;
            hg = ag[i][5]; hu = au[i][5];       o1.y = (hg / (1.f + expf(-hg))) * hu;
            hg = ag[i][6]; hu = au[i][6];       o1.z = (hg / (1.f + expf(-hg))) * hu;
            hg = ag[i][7]; hu = au[i][7];       o1.w = (hg / (1.f + expf(-hg))) * hu;
        }
        *(float4*)(dst + 4 * ng)      = o0;
        *(float4*)(dst + 64 + 4 * ng) = o1;
    }
}

// ============================================================================
// Kernel 3: down-projection + routed scatter-add. Grid (H/NT=16, E, B/MT=4).
// ============================================================================
__global__ void __launch_bounds__(128, 4)
k_down(const float* __restrict__ w2, float* __restrict__ out) {
    int e   = blockIdx.y;
    int cnt = g_count[e];
    int m0  = blockIdx.z * MT;
    if (m0 >= cnt) return;
    int M   = min(MT, cnt - m0);
    int n0  = blockIdx.x * NT;
    int tid = threadIdx.x;
    int warp = tid >> 5;

    __shared__ __align__(16) float ws[KB][WSTR];
    __shared__ __align__(16) float xs[KB][XSTR];
    __shared__ int   toks[MT];
    __shared__ float rw[MT];

    if (tid < MT) {
        int t = (tid < M) ? g_tokens[e * B + m0 + tid] : -1;
        toks[tid] = t;
        rw[tid]   = (t >= 0) ? g_routing[t * E + e] : 0.f;
    }
    __syncthreads();

    int ng = tid & 15;
    int mb = (tid >> 4) * 4;
    bool wactive = (warp * 8) < M;

    int wn = tid >> 2;
    int kq = tid & 3;
    const float* pw = w2 + (size_t)e * H * I + (size_t)(n0 + wn) * I + 4 * kq;
    bool xvalid = (wn < M);
    const float* px = g_inter + ((size_t)e * B + m0 + wn) * I + 4 * kq;

    float4 rs[4], rx;
    #pragma unroll
    for (int r = 0; r < 4; ++r)
        rs[r] = *(const float4*)(pw + (size_t)(32 * r) * I);
    rx = xvalid ? *(const float4*)px : make_float4(0.f, 0.f, 0.f, 0.f);

    float acc[4][8];
    #pragma unroll
    for (int i = 0; i < 4; ++i)
        #pragma unroll
        for (int j = 0; j < 8; ++j) acc[i][j] = 0.f;

    const int NC = I / KB;                // 48 chunks
    for (int c = 0; c < NC; ++c) {
        __syncthreads();
        #pragma unroll
        for (int r = 0; r < 4; ++r) {
            int n = wn + 32 * r;
            ws[4*kq+0][n] = rs[r].x; ws[4*kq+1][n] = rs[r].y;
            ws[4*kq+2][n] = rs[r].z; ws[4*kq+3][n] = rs[r].w;
        }
        xs[4*kq+0][wn] = rx.x; xs[4*kq+1][wn] = rx.y;
        xs[4*kq+2][wn] = rx.z; xs[4*kq+3][wn] = rx.w;
        __syncthreads();

        if (c + 1 < NC) {
            int k0 = (c + 1) * KB;
            #pragma unroll
            for (int r = 0; r < 4; ++r)
                rs[r] = *(const float4*)(pw + (size_t)(32 * r) * I + k0);
            rx = xvalid ? *(const float4*)(px + k0) : make_float4(0.f,0.f,0.f,0.f);
        }

        if (wactive) {
            #pragma unroll 4
            for (int kk = 0; kk < KB; ++kk) {
                float4 xv = *(const float4*)&xs[kk][mb];
                float4 w0 = *(const float4*)&ws[kk][4*ng];
                float4 w1v = *(const float4*)&ws[kk][64 + 4*ng];
                float xm4[4] = {xv.x, xv.y, xv.z, xv.w};
                float wv[8]  = {w0.x,w0.y,w0.z,w0.w, w1v.x,w1v.y,w1v.z,w1v.w};
                #pragma unroll
                for (int i = 0; i < 4; ++i)
                    #pragma unroll
                    for (int j = 0; j < 8; ++j)
                        acc[i][j] += xm4[i] * wv[j];
            }
        }
    }

    #pragma unroll
    for (int i = 0; i < 4; ++i) {
        int m = mb + i;
        if (m >= M) continue;
        float s = rw[m];
        int   b = toks[m];
        float* dst = out + (size_t)b * H + n0;
        #pragma unroll
        for (int j = 0; j < 4; ++j)
            atomicAdd(dst + 4 * ng + j, s * acc[i][j]);
        #pragma unroll
        for (int j = 0; j < 4; ++j)
            atomicAdd(dst + 64 + 4 * ng + j, s * acc[i][4 + j]);
    }
}

// ============================================================================
// Launch
// ============================================================================
extern "C" void kernel_launch(void* const* d_in, const int* in_sizes, int n_in,
                              void* d_out, int out_size) {
    const float* x  = (const float*)d_in[0];   // (128, 2048)
    const float* gw = (const float*)d_in[1];   // (64, 2048)
    const float* w1 = (const float*)d_in[2];   // (64, 1536, 2048)
    const float* w2 = (const float*)d_in[3];   // (64, 2048, 768)
    float* out = (float*)d_out;                // (128, 1, 2048)

    k_zero<<<(B * H + 255) / 256, 256>>>(out);
    k_route<<<B, 256>>>(x, gw);

    dim3 gA(I / NT, E, B / MT);    // (6, 64, 4)
    k_up<<<gA, 128>>>(x, w1);

    dim3 gB(H / NT, E, B / MT);    // (16, 64, 4)
    k_down<<<gB, 128>>>(w2, out);
}

// round 12
// speedup vs baseline: 2.6455x; 1.2484x over previous
#include <cuda_runtime.h>
#include <cuda_bf16.h>
#include <math.h>
#include <stdint.h>

#define B     128
#define H     2048
#define E     64
#define I     768
#define TWO_I 1536
#define TOPK  8

#define SAW   40        // smem row stride in bf16 elems (80 bytes: odd multiple of 16B -> conflict-free ldmatrix)
#define SAWB  80        // bytes

// -------- device-global scratch (no allocations allowed) --------
__device__ float g_routing[B * E];
__device__ int   g_count[E];
__device__ int   g_tokens[E * B];
__device__ float g_h[(size_t)E * B * TWO_I];     // raw gate|up activations (~50 MB)
__device__ float g_inter[(size_t)E * B * I];     // silu(g)*u (~25 MB)

// ======================= helpers =======================
__device__ __forceinline__ uint32_t smem_u32(const void* p) {
    uint32_t a;
    asm("{ .reg .u64 t; cvta.to.shared.u64 t, %1; cvt.u32.u64 %0, t; }" : "=r"(a) : "l"(p));
    return a;
}
__device__ __forceinline__ void ldsm4(uint32_t* r, uint32_t a) {
    asm volatile("ldmatrix.sync.aligned.m8n8.x4.shared.b16 {%0,%1,%2,%3}, [%4];"
        : "=r"(r[0]), "=r"(r[1]), "=r"(r[2]), "=r"(r[3]) : "r"(a));
}
__device__ __forceinline__ void mma_bf16(float* d, const uint32_t* a, const uint32_t* b) {
    asm volatile("mma.sync.aligned.m16n8k16.row.col.f32.bf16.bf16.f32 "
        "{%0,%1,%2,%3}, {%4,%5,%6,%7}, {%8,%9}, {%0,%1,%2,%3};"
        : "+f"(d[0]), "+f"(d[1]), "+f"(d[2]), "+f"(d[3])
        : "r"(a[0]), "r"(a[1]), "r"(a[2]), "r"(a[3]), "r"(b[0]), "r"(b[1]));
}
// split fp32x4 -> hi/lo bf16x2 words (low half of each b32 = lower-k element)
__device__ __forceinline__ void cvt_split(float4 v, uint32_t& h01, uint32_t& h23,
                                          uint32_t& l01, uint32_t& l23) {
    asm("cvt.rn.bf16x2.f32 %0, %1, %2;" : "=r"(h01) : "f"(v.y), "f"(v.x));
    asm("cvt.rn.bf16x2.f32 %0, %1, %2;" : "=r"(h23) : "f"(v.w), "f"(v.z));
    float r0 = v.x - __uint_as_float(h01 << 16);
    float r1 = v.y - __uint_as_float(h01 & 0xffff0000u);
    float r2 = v.z - __uint_as_float(h23 << 16);
    float r3 = v.w - __uint_as_float(h23 & 0xffff0000u);
    asm("cvt.rn.bf16x2.f32 %0, %1, %2;" : "=r"(l01) : "f"(r1), "f"(r0));
    asm("cvt.rn.bf16x2.f32 %0, %1, %2;" : "=r"(l23) : "f"(r3), "f"(r2));
}
__device__ __forceinline__ void sts2(uint32_t addr, uint32_t a, uint32_t b) {
    asm volatile("st.shared.v2.b32 [%0], {%1, %2};" :: "r"(addr), "r"(a), "r"(b));
}

// ============================================================================
// Kernel 0: zero output + counters
// ============================================================================
__global__ void k_zero(float* __restrict__ out) {
    int idx = blockIdx.x * blockDim.x + threadIdx.x;
    if (idx < B * H) out[idx] = 0.f;
    if (idx < E) g_count[idx] = 0;
}

// ============================================================================
// Kernel 1: routing (proven)
// ============================================================================
__global__ void k_route(const float* __restrict__ x, const float* __restrict__ gw) {
    int b = blockIdx.x, tid = threadIdx.x, warp = tid >> 5, lane = tid & 31;
    __shared__ float sl[E];
    const float4* xr = (const float4*)(x + (size_t)b * H);
    for (int j = 0; j < 8; ++j) {
        int e = warp * 8 + j;
        const float4* gr = (const float4*)(gw + (size_t)e * H);
        float acc = 0.f;
        for (int t = lane; t < H / 4; t += 32) {
            float4 xv = xr[t], gv = gr[t];
            acc += xv.x * gv.x + xv.y * gv.y + xv.z * gv.z + xv.w * gv.w;
        }
        #pragma unroll
        for (int o = 16; o > 0; o >>= 1) acc += __shfl_xor_sync(0xffffffffu, acc, o);
        if (lane == 0) sl[e] = acc;
    }
    __syncthreads();
    if (tid == 0) {
        float m = sl[0];
        #pragma unroll
        for (int e = 1; e < E; ++e) m = fmaxf(m, sl[e]);
        float p[E];
        #pragma unroll
        for (int e = 0; e < E; ++e) p[e] = expf(sl[e] - m);
        int sel[TOPK]; float val[TOPK]; float ssum = 0.f;
        for (int k = 0; k < TOPK; ++k) {
            int best = 0; float bv = -1.f;
            for (int e = 0; e < E; ++e) if (p[e] > bv) { bv = p[e]; best = e; }
            sel[k] = best; val[k] = bv; ssum += bv; p[best] = -2.f;
        }
        for (int k = 0; k < TOPK; ++k) {
            int e = sel[k];
            g_routing[b * E + e] = val[k] / ssum;
            int pos = atomicAdd(&g_count[e], 1);
            g_tokens[e * B + pos] = b;
        }
    }
}

// ============================================================================
// HMMA grouped GEMM, phase A: h[slot, n0+row] = w1[e, n0+row, :] . x[token, :]
// Grid (12, E, 4). 128 threads = 4 warps; warp owns 32 rows x 32 tokens.
// K chunks of 16 floats; bf16 hi/lo split, 3 MMA passes.
// ============================================================================
__global__ void __launch_bounds__(128)
k_mma_up(const float* __restrict__ x, const float* __restrict__ w1) {
    int e = blockIdx.y, cnt = g_count[e];
    int m0 = blockIdx.z * 32;
    if (m0 >= cnt) return;
    int n0 = blockIdx.x * 128;
    int tid = threadIdx.x, wid = tid >> 5, lid = tid & 31;

    __shared__ __align__(16) uint16_t Ahi[128 * SAW], Alo[128 * SAW];
    __shared__ __align__(16) uint16_t Bhi[32 * SAW],  Blo[32 * SAW];
    __shared__ int toks[32];

    if (tid < 32) toks[tid] = (m0 + tid < cnt) ? g_tokens[e * B + m0 + tid] : -1;
    __syncthreads();

    // staging: thread -> (row rs+32r, float4 col c4) for A; (row rs, c4) for B
    int rs = tid >> 2;            // 0..31
    int c4 = tid & 3;             // 0..3
    const float* wb = w1 + ((size_t)e * TWO_I + n0 + rs) * H + 4 * c4;
    int tk = toks[rs];
    const float* xb = x + (size_t)(tk >= 0 ? tk : 0) * H + 4 * c4;

    uint32_t aAh = smem_u32(Ahi), aAl = smem_u32(Alo);
    uint32_t aBh = smem_u32(Bhi), aBl = smem_u32(Blo);

    // STS addresses (fixed per thread)
    uint32_t stA = (uint32_t)rs * SAWB + (uint32_t)c4 * 8;
    uint32_t stB = stA;

    // ldmatrix lane addresses
    int arow  = wid * 32 + (lid & 15);
    int akoff = (lid >> 4) * 16;                     // bytes
    uint32_t adAh0 = aAh + (uint32_t)arow * SAWB + akoff;
    uint32_t adAh1 = adAh0 + 16 * SAWB;
    uint32_t adAl0 = aAl + (uint32_t)arow * SAWB + akoff;
    uint32_t adAl1 = adAl0 + 16 * SAWB;
    int btok = (((lid >> 4) & 1) << 3) + (lid & 7);
    int bkoff = ((lid >> 3) & 1) * 16;               // bytes
    uint32_t adBh0 = aBh + (uint32_t)btok * SAWB + bkoff;
    uint32_t adBh1 = adBh0 + 16 * SAWB;
    uint32_t adBl0 = aBl + (uint32_t)btok * SAWB + bkoff;
    uint32_t adBl1 = adBl0 + 16 * SAWB;

    float acc[2][4][4];
    #pragma unroll
    for (int i = 0; i < 2; ++i)
        #pragma unroll
        for (int j = 0; j < 4; ++j)
            #pragma unroll
            for (int r = 0; r < 4; ++r) acc[i][j][r] = 0.f;

    // prefetch chunk 0
    float4 va[4], vb;
    #pragma unroll
    for (int r = 0; r < 4; ++r) va[r] = *(const float4*)(wb + (size_t)(32 * r) * H);
    vb = (tk >= 0) ? *(const float4*)xb : make_float4(0.f, 0.f, 0.f, 0.f);

    const int NC = H / 16;        // 128
    for (int c = 0; c < NC; ++c) {
        __syncthreads();
        #pragma unroll
        for (int r = 0; r < 4; ++r) {
            uint32_t h01, h23, l01, l23;
            cvt_split(va[r], h01, h23, l01, l23);
            uint32_t off = stA + (uint32_t)(32 * r) * SAWB;
            sts2(aAh + off, h01, h23);
            sts2(aAl + off, l01, l23);
        }
        {
            uint32_t h01, h23, l01, l23;
            cvt_split(vb, h01, h23, l01, l23);
            sts2(aBh + stB, h01, h23);
            sts2(aBl + stB, l01, l23);
        }
        __syncthreads();

        if (c + 1 < NC) {
            int k0 = (c + 1) * 16;
            #pragma unroll
            for (int r = 0; r < 4; ++r)
                va[r] = *(const float4*)(wb + (size_t)(32 * r) * H + k0);
            vb = (tk >= 0) ? *(const float4*)(xb + k0) : make_float4(0.f, 0.f, 0.f, 0.f);
        }

        uint32_t ah0[4], ah1[4], al0[4], al1[4], bh0[4], bh1[4], bl0[4], bl1[4];
        ldsm4(ah0, adAh0); ldsm4(ah1, adAh1);
        ldsm4(al0, adAl0); ldsm4(al1, adAl1);
        ldsm4(bh0, adBh0); ldsm4(bh1, adBh1);
        ldsm4(bl0, adBl0); ldsm4(bl1, adBl1);

        // hi*hi
        mma_bf16(acc[0][0], ah0, &bh0[0]); mma_bf16(acc[0][1], ah0, &bh0[2]);
        mma_bf16(acc[0][2], ah0, &bh1[0]); mma_bf16(acc[0][3], ah0, &bh1[2]);
        mma_bf16(acc[1][0], ah1, &bh0[0]); mma_bf16(acc[1][1], ah1, &bh0[2]);
        mma_bf16(acc[1][2], ah1, &bh1[0]); mma_bf16(acc[1][3], ah1, &bh1[2]);
        // hi*lo
        mma_bf16(acc[0][0], ah0, &bl0[0]); mma_bf16(acc[0][1], ah0, &bl0[2]);
        mma_bf16(acc[0][2], ah0, &bl1[0]); mma_bf16(acc[0][3], ah0, &bl1[2]);
        mma_bf16(acc[1][0], ah1, &bl0[0]); mma_bf16(acc[1][1], ah1, &bl0[2]);
        mma_bf16(acc[1][2], ah1, &bl1[0]); mma_bf16(acc[1][3], ah1, &bl1[2]);
        // lo*hi
        mma_bf16(acc[0][0], al0, &bh0[0]); mma_bf16(acc[0][1], al0, &bh0[2]);
        mma_bf16(acc[0][2], al0, &bh1[0]); mma_bf16(acc[0][3], al0, &bh1[2]);
        mma_bf16(acc[1][0], al1, &bh0[0]); mma_bf16(acc[1][1], al1, &bh0[2]);
        mma_bf16(acc[1][2], al1, &bh1[0]); mma_bf16(acc[1][3], al1, &bh1[2]);
    }

    // epilogue: C[row, col] -> g_h[(e*B + m0 + col)*TWO_I + n0 + row]
    int l4 = lid >> 2, l2 = (lid & 3) * 2;
    #pragma unroll
    for (int mt = 0; mt < 2; ++mt)
        #pragma unroll
        for (int nt = 0; nt < 4; ++nt)
            #pragma unroll
            for (int r = 0; r < 4; ++r) {
                int row = wid * 32 + mt * 16 + l4 + (r >> 1) * 8;
                int col = nt * 8 + l2 + (r & 1);
                g_h[((size_t)e * B + m0 + col) * TWO_I + n0 + row] = acc[mt][nt][r];
            }
}

// ============================================================================
// Kernel: silu(gate)*up on valid slots
// ============================================================================
__global__ void k_silu() {
    int e = blockIdx.x, sc = blockIdx.y;
    int cnt = g_count[e];
    int tid = threadIdx.x;
    for (int s = 0; s < 32; ++s) {
        int slot = sc * 32 + s;
        if (slot >= cnt) return;
        const float* gp = g_h + ((size_t)e * B + slot) * TWO_I;
        float* op = g_inter + ((size_t)e * B + slot) * I;
        for (int i = tid; i < I; i += 256) {
            float g = gp[i], u = gp[I + i];
            op[i] = (g / (1.f + expf(-g))) * u;
        }
    }
}

// ============================================================================
// HMMA grouped GEMM, phase B: out[token] += rw * (w2[e] @ inter[slot])
// Grid (16, E, 4). K = I = 768, chunks of 16.
// ============================================================================
__global__ void __launch_bounds__(128)
k_mma_down(const float* __restrict__ w2, float* __restrict__ out) {
    int e = blockIdx.y, cnt = g_count[e];
    int m0 = blockIdx.z * 32;
    if (m0 >= cnt) return;
    int n0 = blockIdx.x * 128;
    int tid = threadIdx.x, wid = tid >> 5, lid = tid & 31;

    __shared__ __align__(16) uint16_t Ahi[128 * SAW], Alo[128 * SAW];
    __shared__ __align__(16) uint16_t Bhi[32 * SAW],  Blo[32 * SAW];
    __shared__ int   toks[32];
    __shared__ float rw[32];

    if (tid < 32) {
        int t = (m0 + tid < cnt) ? g_tokens[e * B + m0 + tid] : -1;
        toks[tid] = t;
        rw[tid]   = (t >= 0) ? g_routing[t * E + e] : 0.f;
    }
    __syncthreads();

    int rs = tid >> 2;
    int c4 = tid & 3;
    const float* wb = w2 + (size_t)e * H * I + (size_t)(n0 + rs) * I + 4 * c4;
    bool bval = (m0 + rs) < cnt;
    const float* ib = g_inter + ((size_t)e * B + m0 + rs) * I + 4 * c4;

    uint32_t aAh = smem_u32(Ahi), aAl = smem_u32(Alo);
    uint32_t aBh = smem_u32(Bhi), aBl = smem_u32(Blo);
    uint32_t stA = (uint32_t)rs * SAWB + (uint32_t)c4 * 8;

    int arow  = wid * 32 + (lid & 15);
    int akoff = (lid >> 4) * 16;
    uint32_t adAh0 = aAh + (uint32_t)arow * SAWB + akoff;
    uint32_t adAh1 = adAh0 + 16 * SAWB;
    uint32_t adAl0 = aAl + (uint32_t)arow * SAWB + akoff;
    uint32_t adAl1 = adAl0 + 16 * SAWB;
    int btok = (((lid >> 4) & 1) << 3) + (lid & 7);
    int bkoff = ((lid >> 3) & 1) * 16;
    uint32_t adBh0 = aBh + (uint32_t)btok * SAWB + bkoff;
    uint32_t adBh1 = adBh0 + 16 * SAWB;
    uint32_t adBl0 = aBl + (uint32_t)btok * SAWB + bkoff;
    uint32_t adBl1 = adBl0 + 16 * SAWB;

    float acc[2][4][4];
    #pragma unroll
    for (int i = 0; i < 2; ++i)
        #pragma unroll
        for (int j = 0; j < 4; ++j)
            #pragma unroll
            for (int r = 0; r < 4; ++r) acc[i][j][r] = 0.f;

    float4 va[4], vb;
    #pragma unroll
    for (int r = 0; r < 4; ++r) va[r] = *(const float4*)(wb + (size_t)(32 * r) * I);
    vb = bval ? *(const float4*)ib : make_float4(0.f, 0.f, 0.f, 0.f);

    const int NC = I / 16;        // 48
    for (int c = 0; c < NC; ++c) {
        __syncthreads();
        #pragma unroll
        for (int r = 0; r < 4; ++r) {
            uint32_t h01, h23, l01, l23;
            cvt_split(va[r], h01, h23, l01, l23);
            uint32_t off = stA + (uint32_t)(32 * r) * SAWB;
            sts2(aAh + off, h01, h23);
            sts2(aAl + off, l01, l23);
        }
        {
            uint32_t h01, h23, l01, l23;
            cvt_split(vb, h01, h23, l01, l23);
            sts2(aBh + stA, h01, h23);
            sts2(aBl + stA, l01, l23);
        }
        __syncthreads();

        if (c + 1 < NC) {
            int k0 = (c + 1) * 16;
            #pragma unroll
            for (int r = 0; r < 4; ++r)
                va[r] = *(const float4*)(wb + (size_t)(32 * r) * I + k0);
            vb = bval ? *(const float4*)(ib + k0) : make_float4(0.f, 0.f, 0.f, 0.f);
        }

        uint32_t ah0[4], ah1[4], al0[4], al1[4], bh0[4], bh1[4], bl0[4], bl1[4];
        ldsm4(ah0, adAh0); ldsm4(ah1, adAh1);
        ldsm4(al0, adAl0); ldsm4(al1, adAl1);
        ldsm4(bh0, adBh0); ldsm4(bh1, adBh1);
        ldsm4(bl0, adBl0); ldsm4(bl1, adBl1);

        mma_bf16(acc[0][0], ah0, &bh0[0]); mma_bf16(acc[0][1], ah0, &bh0[2]);
        mma_bf16(acc[0][2], ah0, &bh1[0]); mma_bf16(acc[0][3], ah0, &bh1[2]);
        mma_bf16(acc[1][0], ah1, &bh0[0]); mma_bf16(acc[1][1], ah1, &bh0[2]);
        mma_bf16(acc[1][2], ah1, &bh1[0]); mma_bf16(acc[1][3], ah1, &bh1[2]);

        mma_bf16(acc[0][0], ah0, &bl0[0]); mma_bf16(acc[0][1], ah0, &bl0[2]);
        mma_bf16(acc[0][2], ah0, &bl1[0]); mma_bf16(acc[0][3], ah0, &bl1[2]);
        mma_bf16(acc[1][0], ah1, &bl0[0]); mma_bf16(acc[1][1], ah1, &bl0[2]);
        mma_bf16(acc[1][2], ah1, &bl1[0]); mma_bf16(acc[1][3], ah1, &bl1[2]);

        mma_bf16(acc[0][0], al0, &bh0[0]); mma_bf16(acc[0][1], al0, &bh0[2]);
        mma_bf16(acc[0][2], al0, &bh1[0]); mma_bf16(acc[0][3], al0, &bh1[2]);
        mma_bf16(acc[1][0], al1, &bh0[0]); mma_bf16(acc[1][1], al1, &bh0[2]);
        mma_bf16(acc[1][2], al1, &bh1[0]); mma_bf16(acc[1][3], al1, &bh1[2]);
    }

    int l4 = lid >> 2, l2 = (lid & 3) * 2;
    #pragma unroll
    for (int mt = 0; mt < 2; ++mt)
        #pragma unroll
        for (int nt = 0; nt < 4; ++nt)
            #pragma unroll
            for (int r = 0; r < 4; ++r) {
                int col = nt * 8 + l2 + (r & 1);
                int t   = toks[col];
                if (t >= 0) {
                    int row = wid * 32 + mt * 16 + l4 + (r >> 1) * 8;
                    atomicAdd(out + (size_t)t * H + n0 + row, rw[col] * acc[mt][nt][r]);
                }
            }
}

// ============================================================================
// Launch
// ============================================================================
extern "C" void kernel_launch(void* const* d_in, const int* in_sizes, int n_in,
                              void* d_out, int out_size) {
    const float* x  = (const float*)d_in[0];   // (128, 2048)
    const float* gw = (const float*)d_in[1];   // (64, 2048)
    const float* w1 = (const float*)d_in[2];   // (64, 1536, 2048)
    const float* w2 = (const float*)d_in[3];   // (64, 2048, 768)
    float* out = (float*)d_out;                // (128, 1, 2048)

    k_zero<<<(B * H + 255) / 256, 256>>>(out);
    k_route<<<B, 256>>>(x, gw);

    dim3 gA(TWO_I / 128, E, B / 32);   // (12, 64, 4)
    k_mma_up<<<gA, 128>>>(x, w1);

    dim3 gS(E, B / 32);                // (64, 4)
    k_silu<<<gS, 256>>>();

    dim3 gB(H / 128, E, B / 32);       // (16, 64, 4)
    k_mma_down<<<gB, 128>>>(w2, out);
}